// round 15
// baseline (speedup 1.0000x reference)
#include <cuda_runtime.h>
#include <cuda_bf16.h>
#include <math.h>
#include <stdint.h>

// ---------------------------------------------------------------------------
// 25-pt (radius-4, 3-axis) wave stencil, 10 scan steps (first trivial),
// then loss = mean((out-ref)^2), max_abs = max|out-ref|.
// R15: R12 with a DEEPER pipeline: rings 3->4 deep, fill distance 2->3,
// wait_group 1->2 (two async groups outstanding per warp; 3 bodies of slack).
// 5 blocks/SM (smem 45KB), reg cap freed to 102 (no R14-style squeeze).
// ---------------------------------------------------------------------------

#define NN 192
#define PLANE (NN * NN)
#define VOL (NN * NN * NN)

#define TXT 16
#define TY 8
#define NTHR (TXT * TY)          // 128
#define SPANX (TXT * 4)          // 64 x-points per block
#define ZC 16
#define R  4

#define TILE_H (TY + 2 * R)      // 16
#define TILE_W 80                // padded row stride (R12-identical)
#define TILE_WU (SPANX + 2 * R)  // 72 floats used
#define FW4 (TILE_WU / 4)        // 18 float4 per row
#define NSLOT (TILE_H * FW4)     // 288 fill slots
#define NBUF 4
#define PWF (NTHR * 4)           // floats per pw field (512)

#define C0 ((float)(-205.0 / 72.0 / 400.0))
#define C1 ((float)(8.0 / 5.0 / 400.0))
#define C2 ((float)(-1.0 / 5.0 / 400.0))
#define C3 ((float)(8.0 / 315.0 / 400.0))
#define C4 ((float)(-1.0 / 560.0 / 400.0))

__device__ float g_bufA[VOL];
__device__ float g_bufB[VOL];
__device__ double g_sum;
__device__ unsigned int g_maxbits;

__global__ void init_accum_kernel() {
    g_sum = 0.0;
    g_maxbits = 0u;
}

__device__ __forceinline__ float4 ldg4(const float* p) {
    return *reinterpret_cast<const float4*>(p);
}
__device__ __forceinline__ float ldcs1(const float* p) {
    float v;
    asm volatile("ld.global.cs.f32 %0, [%1];" : "=f"(v) : "l"(p));
    return v;
}

// Stencil tile fill (cp.async, NO commit)
__device__ __forceinline__ void fill_plane(
    uint32_t sbase, const float* gplane, const int* goff, const int* sidx) {
#pragma unroll
    for (int k = 0; k < 3; k++) {
        if (sidx[k] >= 0) {
            const float* srcp = (goff[k] >= 0) ? (gplane + goff[k]) : gplane;
            int sz = (goff[k] >= 0) ? 16 : 0;
            asm volatile("cp.async.cg.shared.global [%0], [%1], 16, %2;"
                         :: "r"(sbase + (uint32_t)sidx[k] * 4u), "l"(srcp), "r"(sz));
        }
    }
}

// Pointwise fill: prev/vp/src quads for one plane (NO commit).
__device__ __forceinline__ void fill_pw(
    uint32_t pwbase, const float* prev, const float* vp, const float* src,
    int idx, bool hasprev, int tid) {
    uint32_t d = pwbase + (uint32_t)tid * 16u;
    if (hasprev) {
        asm volatile("cp.async.cg.shared.global [%0], [%1], 16;"
                     :: "r"(d), "l"(prev + idx));
    }
    asm volatile("cp.async.cg.shared.global [%0], [%1], 16;"
                 :: "r"(d + PWF * 4u), "l"(vp + idx));
    asm volatile("cp.async.cg.shared.global [%0], [%1], 16;"
                 :: "r"(d + 2u * PWF * 4u), "l"(src + idx));
}

// 25-pt laplacian for one plane from tile t + 9 z-queue values.
__device__ __forceinline__ float4 lap25(
    const float (&t)[TILE_H][TILE_W], int sx, int syc,
    const float4& qm4, const float4& qm3, const float4& qm2, const float4& qm1,
    const float4& qc,
    const float4& qp1, const float4& qp2, const float4& qp3, const float4& qp4) {

    float xs[12];
#pragma unroll
    for (int j = 0; j < 3; j++) {
        float4 v = *reinterpret_cast<const float4*>(&t[syc][sx - 4 + 4 * j]);
        xs[4 * j + 0] = v.x;
        xs[4 * j + 1] = v.y;
        xs[4 * j + 2] = v.z;
        xs[4 * j + 3] = v.w;
    }

    float lap[4];
    {
        const float* q4 = &qc.x;
#pragma unroll
        for (int p = 0; p < 4; p++) lap[p] = (3.0f * C0) * q4[p];
    }
    {
        float4 ym = *reinterpret_cast<const float4*>(&t[syc - 1][sx]);
        float4 yp = *reinterpret_cast<const float4*>(&t[syc + 1][sx]);
        const float* a = &ym.x; const float* b = &yp.x;
        const float* m = &qm1.x; const float* pl = &qp1.x;
#pragma unroll
        for (int p = 0; p < 4; p++)
            lap[p] += C1 * (m[p] + pl[p] + a[p] + b[p] + xs[p + 3] + xs[p + 5]);
    }
    {
        float4 ym = *reinterpret_cast<const float4*>(&t[syc - 2][sx]);
        float4 yp = *reinterpret_cast<const float4*>(&t[syc + 2][sx]);
        const float* a = &ym.x; const float* b = &yp.x;
        const float* m = &qm2.x; const float* pl = &qp2.x;
#pragma unroll
        for (int p = 0; p < 4; p++)
            lap[p] += C2 * (m[p] + pl[p] + a[p] + b[p] + xs[p + 2] + xs[p + 6]);
    }
    {
        float4 ym = *reinterpret_cast<const float4*>(&t[syc - 3][sx]);
        float4 yp = *reinterpret_cast<const float4*>(&t[syc + 3][sx]);
        const float* a = &ym.x; const float* b = &yp.x;
        const float* m = &qm3.x; const float* pl = &qp3.x;
#pragma unroll
        for (int p = 0; p < 4; p++)
            lap[p] += C3 * (m[p] + pl[p] + a[p] + b[p] + xs[p + 1] + xs[p + 7]);
    }
    {
        float4 ym = *reinterpret_cast<const float4*>(&t[syc - 4][sx]);
        float4 yp = *reinterpret_cast<const float4*>(&t[syc + 4][sx]);
        const float* a = &ym.x; const float* b = &yp.x;
        const float* m = &qm4.x; const float* pl = &qp4.x;
#pragma unroll
        for (int p = 0; p < 4; p++)
            lap[p] += C4 * (m[p] + pl[p] + a[p] + b[p] + xs[p] + xs[p + 8]);
    }
    return make_float4(lap[0], lap[1], lap[2], lap[3]);
}

// Body for plane z:
//  wait_group 2 -> barrier -> fill S(z+3)+PW(z+3), ONE commit -> q-head
//  LDG(z+5) -> LDS pv/vv/sv -> compute -> store.
template <bool FINAL>
__device__ __forceinline__ void plane_body(
    const float* __restrict__ cur, const float* __restrict__ prev,
    const float* __restrict__ vp, const float* __restrict__ src,
    float* __restrict__ out, const float* __restrict__ ref,
    const float (&consume)[TILE_H][TILE_W],
    const float* pwcons,
    uint32_t fill_sb, uint32_t fill_pb,
    int z, bool hasprev,
    const int* goff, const int* sidx, int col, int tid,
    float4& qm4, float4& qm3, float4& qm2, float4& qm1, float4& qc,
    float4& qp1, float4& qp2, float4& qp3, float4& qp4,
    int sx, int syc,
    double& acc_s, float& acc_m) {

    const int idx = z * PLANE + col;

    // plane z's group forced complete (committed 3 bodies ago); 2 outstanding
    asm volatile("cp.async.wait_group 2;" ::: "memory");
    __syncthreads();

    // fills for plane z+3 (slot consumed at body z-1 -> safe post-barrier)
    {
        int zf = z + 3; if (zf > NN - 1) zf = NN - 1;
        fill_plane(fill_sb, cur + zf * PLANE, goff, sidx);
        fill_pw(fill_pb, prev, vp, src, zf * PLANE + col, hasprev, tid);
        asm volatile("cp.async.commit_group;" ::: "memory");
    }

    // q-head prefetch for NEXT body (plane z+5)
    float4 qn;
    {
        int zp = z + 5;
        qn = (zp < NN) ? ldg4(&cur[zp * PLANE + col]) : make_float4(0.f, 0.f, 0.f, 0.f);
    }

    const float4 pv = hasprev
        ? *reinterpret_cast<const float4*>(pwcons + 4 * tid)
        : make_float4(0.f, 0.f, 0.f, 0.f);
    const float4 vv = *reinterpret_cast<const float4*>(pwcons + PWF + 4 * tid);
    const float4 sv = *reinterpret_cast<const float4*>(pwcons + 2 * PWF + 4 * tid);

    float4 lp = lap25(consume, sx, syc, qm4, qm3, qm2, qm1, qc, qp1, qp2, qp3, qp4);

    float4 upd;
    {
        const float* q4 = &qc.x;
        const float* pvp = &pv.x; const float* vvp = &vv.x; const float* svp = &sv.x;
        const float* lpp = &lp.x; float* u = &upd.x;
#pragma unroll
        for (int p = 0; p < 4; p++)
            u[p] = 2.0f * q4[p] - pvp[p] + vvp[p] * lpp[p] + svp[p];
    }

    if (FINAL) {
        const float* u = &upd.x;
#pragma unroll
        for (int p = 0; p < 4; p++) {
            out[idx + p] = u[p];
            float e = u[p] - ldcs1(&ref[idx + p]);
            acc_s += (double)e * (double)e;
            acc_m = fmaxf(acc_m, fabsf(e));
        }
    } else {
        *reinterpret_cast<float4*>(&out[idx]) = upd;
    }

    qm4 = qn;   // rotation: becomes next body's qp4
}

template <bool FINAL>
__global__ void __launch_bounds__(NTHR, 5)
step_kernel(const float* __restrict__ cur,
            const float* __restrict__ prev,
            const float* __restrict__ vp,
            const float* __restrict__ src,
            float* __restrict__ out,
            const float* __restrict__ ref) {
    __shared__ float sp[NBUF][TILE_H][TILE_W];    // 4 x 5120 B
    __shared__ float pwr[NBUF][3 * PWF];          // 4 x 6144 B

    const int tx = threadIdx.x;
    const int ty = threadIdx.y;
    const int x0 = blockIdx.x * SPANX;
    const int y0 = blockIdx.y * TY;
    const int z0 = blockIdx.z * ZC;
    const int gx = x0 + 4 * tx;
    const int gy = y0 + ty;
    const int tid = ty * TXT + tx;
    const int col = gy * NN + gx;

    int goff[3], sidx[3];
#pragma unroll
    for (int k = 0; k < 3; k++) {
        int i = tid + k * NTHR;
        if (i < NSLOT) {
            int sy = i / FW4;
            int sxx = i - sy * FW4;
            int yy = y0 - R + sy;
            int xx = x0 - R + 4 * sxx;
            sidx[k] = sy * TILE_W + 4 * sxx;
            goff[k] = (xx >= 0 && xx + 3 < NN && yy >= 0 && yy < NN)
                          ? (yy * NN + xx) : -1;
        } else {
            sidx[k] = -1;
            goff[k] = -1;
        }
    }

    uint32_t sb[NBUF], pb[NBUF];
#pragma unroll
    for (int b = 0; b < NBUF; b++) {
        sb[b] = (uint32_t)__cvta_generic_to_shared(&sp[b][0][0]);
        pb[b] = (uint32_t)__cvta_generic_to_shared(&pwr[b][0]);
    }

    const bool hasprev = (prev != nullptr);

    // Prologue: groups for planes z0, z0+1, z0+2 (slots 0,1,2)
    fill_plane(sb[0], cur + z0 * PLANE, goff, sidx);
    fill_pw(pb[0], prev, vp, src, z0 * PLANE + col, hasprev, tid);
    asm volatile("cp.async.commit_group;" ::: "memory");
    fill_plane(sb[1], cur + (z0 + 1) * PLANE, goff, sidx);
    fill_pw(pb[1], prev, vp, src, (z0 + 1) * PLANE + col, hasprev, tid);
    asm volatile("cp.async.commit_group;" ::: "memory");
    fill_plane(sb[2], cur + (z0 + 2) * PLANE, goff, sidx);
    fill_pw(pb[2], prev, vp, src, (z0 + 2) * PLANE + col, hasprev, tid);
    asm volatile("cp.async.commit_group;" ::: "memory");

    // z-queue: 9 named registers, planes z0-4 .. z0+4
    float4 r0, r1, r2, r3, r4, r5, r6, r7, r8;
    {
        float4* rr[9] = {&r0, &r1, &r2, &r3, &r4, &r5, &r6, &r7, &r8};
#pragma unroll
        for (int k = 0; k < 9; k++) {
            int gz = z0 - R + k;
            *rr[k] = (gz >= 0 && gz < NN) ? ldg4(&cur[gz * PLANE + col])
                                          : make_float4(0.f, 0.f, 0.f, 0.f);
        }
    }

    const int sx = R + 4 * tx;
    const int syc = ty + R;

    double acc_s = 0.0;
    float acc_m = 0.0f;

    // 16 unrolled bodies. Consume slot I%4; fill slot (I+3)%4 with plane z+3.
    // Queue rotated by argument order (period 9).
#define PB(I, A, B, C, D, E, F, G, H, J)                                      \
    plane_body<FINAL>(cur, prev, vp, src, out, ref,                          \
                      sp[(I) % 4], &pwr[(I) % 4][0],                         \
                      sb[((I) + 3) % 4], pb[((I) + 3) % 4],                  \
                      z0 + (I), hasprev, goff, sidx, col, tid,               \
                      r##A, r##B, r##C, r##D, r##E, r##F, r##G, r##H, r##J,  \
                      sx, syc, acc_s, acc_m)

    PB(0, 0, 1, 2, 3, 4, 5, 6, 7, 8);
    PB(1, 1, 2, 3, 4, 5, 6, 7, 8, 0);
    PB(2, 2, 3, 4, 5, 6, 7, 8, 0, 1);
    PB(3, 3, 4, 5, 6, 7, 8, 0, 1, 2);
    PB(4, 4, 5, 6, 7, 8, 0, 1, 2, 3);
    PB(5, 5, 6, 7, 8, 0, 1, 2, 3, 4);
    PB(6, 6, 7, 8, 0, 1, 2, 3, 4, 5);
    PB(7, 7, 8, 0, 1, 2, 3, 4, 5, 6);
    PB(8, 8, 0, 1, 2, 3, 4, 5, 6, 7);
    PB(9, 0, 1, 2, 3, 4, 5, 6, 7, 8);
    PB(10, 1, 2, 3, 4, 5, 6, 7, 8, 0);
    PB(11, 2, 3, 4, 5, 6, 7, 8, 0, 1);
    PB(12, 3, 4, 5, 6, 7, 8, 0, 1, 2);
    PB(13, 4, 5, 6, 7, 8, 0, 1, 2, 3);
    PB(14, 5, 6, 7, 8, 0, 1, 2, 3, 4);
    PB(15, 6, 7, 8, 0, 1, 2, 3, 4, 5);
#undef PB

    if (FINAL) {
#pragma unroll
        for (int o = 16; o > 0; o >>= 1) {
            acc_s += __shfl_down_sync(0xFFFFFFFFu, acc_s, o);
            acc_m = fmaxf(acc_m, __shfl_down_sync(0xFFFFFFFFu, acc_m, o));
        }
        __shared__ double ss[4];
        __shared__ float sm[4];
        int lane = tid & 31;
        int w = tid >> 5;
        if (lane == 0) { ss[w] = acc_s; sm[w] = acc_m; }
        __syncthreads();
        if (w == 0) {
            acc_s = (lane < 4) ? ss[lane] : 0.0;
            acc_m = (lane < 4) ? sm[lane] : 0.0f;
#pragma unroll
            for (int o = 2; o > 0; o >>= 1) {
                acc_s += __shfl_down_sync(0xFFFFFFFFu, acc_s, o);
                acc_m = fmaxf(acc_m, __shfl_down_sync(0xFFFFFFFFu, acc_m, o));
            }
            if (lane == 0) {
                atomicAdd(&g_sum, acc_s);
                atomicMax(&g_maxbits, __float_as_uint(acc_m));
            }
        }
    }
}

__global__ void finalize_kernel(float* d_out, int n) {
    d_out[0] = (float)(g_sum / (double)n);
    d_out[n + 1] = __uint_as_float(g_maxbits);
}

extern "C" void kernel_launch(void* const* d_in, const int* in_sizes, int n_in,
                              void* d_out, int out_size) {
    const float* vp  = (const float*)d_in[0];
    const float* src = (const float*)d_in[1];
    const float* ref = (const float*)d_in[2];

    static float* bufA = nullptr;
    static float* bufB = nullptr;
    if (!bufA) {
        cudaGetSymbolAddress((void**)&bufA, g_bufA);
        cudaGetSymbolAddress((void**)&bufB, g_bufB);
    }

    const bool has_scalars = (out_size >= VOL + 2);
    float* outp = has_scalars ? ((float*)d_out + 1) : (float*)d_out;

    dim3 blk(TXT, TY);
    dim3 grid(NN / SPANX, NN / TY, NN / ZC);   // (3, 24, 12) = 864 blocks

    init_accum_kernel<<<1, 1>>>();

    const float* s0 = src;

    step_kernel<false><<<grid, blk>>>(s0,   nullptr, vp, src + (size_t)1 * VOL, bufA, nullptr);
    step_kernel<false><<<grid, blk>>>(bufA, s0,      vp, src + (size_t)2 * VOL, bufB, nullptr);
    step_kernel<false><<<grid, blk>>>(bufB, bufA,    vp, src + (size_t)3 * VOL, bufA, nullptr);
    step_kernel<false><<<grid, blk>>>(bufA, bufB,    vp, src + (size_t)4 * VOL, bufB, nullptr);
    step_kernel<false><<<grid, blk>>>(bufB, bufA,    vp, src + (size_t)5 * VOL, bufA, nullptr);
    step_kernel<false><<<grid, blk>>>(bufA, bufB,    vp, src + (size_t)6 * VOL, bufB, nullptr);
    step_kernel<false><<<grid, blk>>>(bufB, bufA,    vp, src + (size_t)7 * VOL, bufA, nullptr);
    step_kernel<false><<<grid, blk>>>(bufA, bufB,    vp, src + (size_t)8 * VOL, bufB, nullptr);
    step_kernel<true><<<grid, blk>>>(bufB, bufA,     vp, src + (size_t)9 * VOL, outp, ref);

    if (has_scalars) {
        finalize_kernel<<<1, 1>>>((float*)d_out, VOL);
    }
}

// round 16
// speedup vs baseline: 1.1063x; 1.1063x over previous
#include <cuda_runtime.h>
#include <cuda_bf16.h>
#include <math.h>
#include <stdint.h>

// ---------------------------------------------------------------------------
// 25-pt (radius-4, 3-axis) wave stencil, 10 scan steps (first trivial),
// then loss = mean((out-ref)^2), max_abs = max|out-ref|.
// R16: R12 champion + q-head moved into the pw cp.async ring (4th field,
// cur[z+5] column quad, zero-filled OOB) -> NO per-body LDG remains; all
// DRAM-latency loads have >=2 bodies of slack. Tile stride 80->72 keeps
// smem at 37.5KB -> 6 blocks/SM, launch_bounds(128,6) (regs free ~80).
// ---------------------------------------------------------------------------

#define NN 192
#define PLANE (NN * NN)
#define VOL (NN * NN * NN)

#define TXT 16
#define TY 8
#define NTHR (TXT * TY)          // 128
#define SPANX (TXT * 4)          // 64 x-points per block
#define ZC 16
#define R  4

#define TILE_H (TY + 2 * R)      // 16
#define TILE_W 72                // row stride (288 B, 16B multiple)
#define FW4 (TILE_W / 4)         // 18 float4 per row
#define NSLOT (TILE_H * FW4)     // 288 fill slots
#define NBUF 3
#define PWF (NTHR * 4)           // floats per pw field (512)
#define NPWFIELD 4               // prev, vp, src, q-head(cur z+5)

#define C0 ((float)(-205.0 / 72.0 / 400.0))
#define C1 ((float)(8.0 / 5.0 / 400.0))
#define C2 ((float)(-1.0 / 5.0 / 400.0))
#define C3 ((float)(8.0 / 315.0 / 400.0))
#define C4 ((float)(-1.0 / 560.0 / 400.0))

__device__ float g_bufA[VOL];
__device__ float g_bufB[VOL];
__device__ double g_sum;
__device__ unsigned int g_maxbits;

__global__ void init_accum_kernel() {
    g_sum = 0.0;
    g_maxbits = 0u;
}

__device__ __forceinline__ float4 ldg4(const float* p) {
    return *reinterpret_cast<const float4*>(p);
}
__device__ __forceinline__ float ldcs1(const float* p) {
    float v;
    asm volatile("ld.global.cs.f32 %0, [%1];" : "=f"(v) : "l"(p));
    return v;
}

// Stencil tile fill (cp.async, NO commit)
__device__ __forceinline__ void fill_plane(
    uint32_t sbase, const float* gplane, const int* goff, const int* sidx) {
#pragma unroll
    for (int k = 0; k < 3; k++) {
        if (sidx[k] >= 0) {
            const float* srcp = (goff[k] >= 0) ? (gplane + goff[k]) : gplane;
            int sz = (goff[k] >= 0) ? 16 : 0;
            asm volatile("cp.async.cg.shared.global [%0], [%1], 16, %2;"
                         :: "r"(sbase + (uint32_t)sidx[k] * 4u), "l"(srcp), "r"(sz));
        }
    }
}

// Pointwise fill for the slot of plane zf (NO commit):
//   field0 prev[zf], field1 vp[zf], field2 src[zf], field3 cur[zf+5] (q-head,
//   zero-filled when zf+5 >= NN to match _shift_zero semantics).
__device__ __forceinline__ void fill_pw(
    uint32_t pwbase, const float* prev, const float* vp, const float* src,
    const float* cur, int zf, int col, bool hasprev, int tid) {
    const int idx = zf * PLANE + col;
    uint32_t d = pwbase + (uint32_t)tid * 16u;
    if (hasprev) {
        asm volatile("cp.async.cg.shared.global [%0], [%1], 16;"
                     :: "r"(d), "l"(prev + idx));
    }
    asm volatile("cp.async.cg.shared.global [%0], [%1], 16;"
                 :: "r"(d + PWF * 4u), "l"(vp + idx));
    asm volatile("cp.async.cg.shared.global [%0], [%1], 16;"
                 :: "r"(d + 2u * PWF * 4u), "l"(src + idx));
    {
        int zq = zf + 5;
        const float* qsrc = (zq < NN) ? (cur + zq * PLANE + col) : (cur + col);
        int sz = (zq < NN) ? 16 : 0;
        asm volatile("cp.async.cg.shared.global [%0], [%1], 16, %2;"
                     :: "r"(d + 3u * PWF * 4u), "l"(qsrc), "r"(sz));
    }
}

// 25-pt laplacian for one plane from tile t + 9 z-queue values.
__device__ __forceinline__ float4 lap25(
    const float (&t)[TILE_H][TILE_W], int sx, int syc,
    const float4& qm4, const float4& qm3, const float4& qm2, const float4& qm1,
    const float4& qc,
    const float4& qp1, const float4& qp2, const float4& qp3, const float4& qp4) {

    float xs[12];
#pragma unroll
    for (int j = 0; j < 3; j++) {
        float4 v = *reinterpret_cast<const float4*>(&t[syc][sx - 4 + 4 * j]);
        xs[4 * j + 0] = v.x;
        xs[4 * j + 1] = v.y;
        xs[4 * j + 2] = v.z;
        xs[4 * j + 3] = v.w;
    }

    float lap[4];
    {
        const float* q4 = &qc.x;
#pragma unroll
        for (int p = 0; p < 4; p++) lap[p] = (3.0f * C0) * q4[p];
    }
    {
        float4 ym = *reinterpret_cast<const float4*>(&t[syc - 1][sx]);
        float4 yp = *reinterpret_cast<const float4*>(&t[syc + 1][sx]);
        const float* a = &ym.x; const float* b = &yp.x;
        const float* m = &qm1.x; const float* pl = &qp1.x;
#pragma unroll
        for (int p = 0; p < 4; p++)
            lap[p] += C1 * (m[p] + pl[p] + a[p] + b[p] + xs[p + 3] + xs[p + 5]);
    }
    {
        float4 ym = *reinterpret_cast<const float4*>(&t[syc - 2][sx]);
        float4 yp = *reinterpret_cast<const float4*>(&t[syc + 2][sx]);
        const float* a = &ym.x; const float* b = &yp.x;
        const float* m = &qm2.x; const float* pl = &qp2.x;
#pragma unroll
        for (int p = 0; p < 4; p++)
            lap[p] += C2 * (m[p] + pl[p] + a[p] + b[p] + xs[p + 2] + xs[p + 6]);
    }
    {
        float4 ym = *reinterpret_cast<const float4*>(&t[syc - 3][sx]);
        float4 yp = *reinterpret_cast<const float4*>(&t[syc + 3][sx]);
        const float* a = &ym.x; const float* b = &yp.x;
        const float* m = &qm3.x; const float* pl = &qp3.x;
#pragma unroll
        for (int p = 0; p < 4; p++)
            lap[p] += C3 * (m[p] + pl[p] + a[p] + b[p] + xs[p + 1] + xs[p + 7]);
    }
    {
        float4 ym = *reinterpret_cast<const float4*>(&t[syc - 4][sx]);
        float4 yp = *reinterpret_cast<const float4*>(&t[syc + 4][sx]);
        const float* a = &ym.x; const float* b = &yp.x;
        const float* m = &qm4.x; const float* pl = &qp4.x;
#pragma unroll
        for (int p = 0; p < 4; p++)
            lap[p] += C4 * (m[p] + pl[p] + a[p] + b[p] + xs[p] + xs[p + 8]);
    }
    return make_float4(lap[0], lap[1], lap[2], lap[3]);
}

// Body for plane z (R12 cadence, q-head from smem):
//  wait_group 1 -> barrier -> fill S(z+2)+PW(z+2), ONE commit ->
//  LDS pv/vv/sv/qn -> compute -> store. Outgoing qm4 takes qn (plane z+5).
template <bool FINAL>
__device__ __forceinline__ void plane_body(
    const float* __restrict__ cur, const float* __restrict__ prev,
    const float* __restrict__ vp, const float* __restrict__ src,
    float* __restrict__ out, const float* __restrict__ ref,
    const float (&consume)[TILE_H][TILE_W],
    const float* pwcons,
    uint32_t fill_sb, uint32_t fill_pb,
    int z, bool hasprev,
    const int* goff, const int* sidx, int col, int tid,
    float4& qm4, float4& qm3, float4& qm2, float4& qm1, float4& qc,
    float4& qp1, float4& qp2, float4& qp3, float4& qp4,
    int sx, int syc,
    double& acc_s, float& acc_m) {

    const int idx = z * PLANE + col;

    asm volatile("cp.async.wait_group 1;" ::: "memory");
    __syncthreads();

    // fills for plane z+2 (slot consumed at body z-1 -> safe post-barrier)
    {
        int zf = z + 2; if (zf > NN - 1) zf = NN - 1;
        fill_plane(fill_sb, cur + zf * PLANE, goff, sidx);
        fill_pw(fill_pb, prev, vp, src, cur, zf, col, hasprev, tid);
        asm volatile("cp.async.commit_group;" ::: "memory");
    }

    // pointwise operands + q-head from smem (all >=2 bodies of async slack)
    const float4 pv = hasprev
        ? *reinterpret_cast<const float4*>(pwcons + 4 * tid)
        : make_float4(0.f, 0.f, 0.f, 0.f);
    const float4 vv = *reinterpret_cast<const float4*>(pwcons + PWF + 4 * tid);
    const float4 sv = *reinterpret_cast<const float4*>(pwcons + 2 * PWF + 4 * tid);
    const float4 qn = *reinterpret_cast<const float4*>(pwcons + 3 * PWF + 4 * tid);

    float4 lp = lap25(consume, sx, syc, qm4, qm3, qm2, qm1, qc, qp1, qp2, qp3, qp4);

    float4 upd;
    {
        const float* q4 = &qc.x;
        const float* pvp = &pv.x; const float* vvp = &vv.x; const float* svp = &sv.x;
        const float* lpp = &lp.x; float* u = &upd.x;
#pragma unroll
        for (int p = 0; p < 4; p++)
            u[p] = 2.0f * q4[p] - pvp[p] + vvp[p] * lpp[p] + svp[p];
    }

    if (FINAL) {
        const float* u = &upd.x;
#pragma unroll
        for (int p = 0; p < 4; p++) {
            out[idx + p] = u[p];
            float e = u[p] - ldcs1(&ref[idx + p]);
            acc_s += (double)e * (double)e;
            acc_m = fmaxf(acc_m, fabsf(e));
        }
    } else {
        *reinterpret_cast<float4*>(&out[idx]) = upd;
    }

    qm4 = qn;   // rotation: becomes next body's qp4 (plane z+5)
}

template <bool FINAL>
__global__ void __launch_bounds__(NTHR, 6)
step_kernel(const float* __restrict__ cur,
            const float* __restrict__ prev,
            const float* __restrict__ vp,
            const float* __restrict__ src,
            float* __restrict__ out,
            const float* __restrict__ ref) {
    __shared__ float sp[NBUF][TILE_H][TILE_W];       // 3 x 4608 B
    __shared__ float pwr[NBUF][NPWFIELD * PWF];      // 3 x 8192 B

    const int tx = threadIdx.x;
    const int ty = threadIdx.y;
    const int x0 = blockIdx.x * SPANX;
    const int y0 = blockIdx.y * TY;
    const int z0 = blockIdx.z * ZC;
    const int gx = x0 + 4 * tx;
    const int gy = y0 + ty;
    const int tid = ty * TXT + tx;
    const int col = gy * NN + gx;

    int goff[3], sidx[3];
#pragma unroll
    for (int k = 0; k < 3; k++) {
        int i = tid + k * NTHR;
        if (i < NSLOT) {
            int sy = i / FW4;
            int sxx = i - sy * FW4;
            int yy = y0 - R + sy;
            int xx = x0 - R + 4 * sxx;
            sidx[k] = sy * TILE_W + 4 * sxx;
            goff[k] = (xx >= 0 && xx + 3 < NN && yy >= 0 && yy < NN)
                          ? (yy * NN + xx) : -1;
        } else {
            sidx[k] = -1;
            goff[k] = -1;
        }
    }

    uint32_t sb[NBUF], pb[NBUF];
#pragma unroll
    for (int b = 0; b < NBUF; b++) {
        sb[b] = (uint32_t)__cvta_generic_to_shared(&sp[b][0][0]);
        pb[b] = (uint32_t)__cvta_generic_to_shared(&pwr[b][0]);
    }

    const bool hasprev = (prev != nullptr);

    // Prologue: groups for planes z0 (slot 0) and z0+1 (slot 1)
    fill_plane(sb[0], cur + z0 * PLANE, goff, sidx);
    fill_pw(pb[0], prev, vp, src, cur, z0, col, hasprev, tid);
    asm volatile("cp.async.commit_group;" ::: "memory");
    fill_plane(sb[1], cur + (z0 + 1) * PLANE, goff, sidx);
    fill_pw(pb[1], prev, vp, src, cur, z0 + 1, col, hasprev, tid);
    asm volatile("cp.async.commit_group;" ::: "memory");

    // z-queue: 9 named registers, planes z0-4 .. z0+4
    float4 r0, r1, r2, r3, r4, r5, r6, r7, r8;
    {
        float4* rr[9] = {&r0, &r1, &r2, &r3, &r4, &r5, &r6, &r7, &r8};
#pragma unroll
        for (int k = 0; k < 9; k++) {
            int gz = z0 - R + k;
            *rr[k] = (gz >= 0 && gz < NN) ? ldg4(&cur[gz * PLANE + col])
                                          : make_float4(0.f, 0.f, 0.f, 0.f);
        }
    }

    const int sx = R + 4 * tx;
    const int syc = ty + R;

    double acc_s = 0.0;
    float acc_m = 0.0f;

    // 16 unrolled bodies. Consume slot I%3; fill slot (I+2)%3.
    // Queue rotated by argument order (period 9).
#define PB(I, A, B, C, D, E, F, G, H, J)                                      \
    plane_body<FINAL>(cur, prev, vp, src, out, ref,                          \
                      sp[(I) % 3], &pwr[(I) % 3][0],                         \
                      sb[((I) + 2) % 3], pb[((I) + 2) % 3],                  \
                      z0 + (I), hasprev, goff, sidx, col, tid,               \
                      r##A, r##B, r##C, r##D, r##E, r##F, r##G, r##H, r##J,  \
                      sx, syc, acc_s, acc_m)

    PB(0, 0, 1, 2, 3, 4, 5, 6, 7, 8);
    PB(1, 1, 2, 3, 4, 5, 6, 7, 8, 0);
    PB(2, 2, 3, 4, 5, 6, 7, 8, 0, 1);
    PB(3, 3, 4, 5, 6, 7, 8, 0, 1, 2);
    PB(4, 4, 5, 6, 7, 8, 0, 1, 2, 3);
    PB(5, 5, 6, 7, 8, 0, 1, 2, 3, 4);
    PB(6, 6, 7, 8, 0, 1, 2, 3, 4, 5);
    PB(7, 7, 8, 0, 1, 2, 3, 4, 5, 6);
    PB(8, 8, 0, 1, 2, 3, 4, 5, 6, 7);
    PB(9, 0, 1, 2, 3, 4, 5, 6, 7, 8);
    PB(10, 1, 2, 3, 4, 5, 6, 7, 8, 0);
    PB(11, 2, 3, 4, 5, 6, 7, 8, 0, 1);
    PB(12, 3, 4, 5, 6, 7, 8, 0, 1, 2);
    PB(13, 4, 5, 6, 7, 8, 0, 1, 2, 3);
    PB(14, 5, 6, 7, 8, 0, 1, 2, 3, 4);
    PB(15, 6, 7, 8, 0, 1, 2, 3, 4, 5);
#undef PB

    if (FINAL) {
#pragma unroll
        for (int o = 16; o > 0; o >>= 1) {
            acc_s += __shfl_down_sync(0xFFFFFFFFu, acc_s, o);
            acc_m = fmaxf(acc_m, __shfl_down_sync(0xFFFFFFFFu, acc_m, o));
        }
        __shared__ double ss[4];
        __shared__ float sm[4];
        int lane = tid & 31;
        int w = tid >> 5;
        if (lane == 0) { ss[w] = acc_s; sm[w] = acc_m; }
        __syncthreads();
        if (w == 0) {
            acc_s = (lane < 4) ? ss[lane] : 0.0;
            acc_m = (lane < 4) ? sm[lane] : 0.0f;
#pragma unroll
            for (int o = 2; o > 0; o >>= 1) {
                acc_s += __shfl_down_sync(0xFFFFFFFFu, acc_s, o);
                acc_m = fmaxf(acc_m, __shfl_down_sync(0xFFFFFFFFu, acc_m, o));
            }
            if (lane == 0) {
                atomicAdd(&g_sum, acc_s);
                atomicMax(&g_maxbits, __float_as_uint(acc_m));
            }
        }
    }
}

__global__ void finalize_kernel(float* d_out, int n) {
    d_out[0] = (float)(g_sum / (double)n);
    d_out[n + 1] = __uint_as_float(g_maxbits);
}

extern "C" void kernel_launch(void* const* d_in, const int* in_sizes, int n_in,
                              void* d_out, int out_size) {
    const float* vp  = (const float*)d_in[0];
    const float* src = (const float*)d_in[1];
    const float* ref = (const float*)d_in[2];

    static float* bufA = nullptr;
    static float* bufB = nullptr;
    if (!bufA) {
        cudaGetSymbolAddress((void**)&bufA, g_bufA);
        cudaGetSymbolAddress((void**)&bufB, g_bufB);
    }

    const bool has_scalars = (out_size >= VOL + 2);
    float* outp = has_scalars ? ((float*)d_out + 1) : (float*)d_out;

    dim3 blk(TXT, TY);
    dim3 grid(NN / SPANX, NN / TY, NN / ZC);   // (3, 24, 12) = 864 blocks

    init_accum_kernel<<<1, 1>>>();

    const float* s0 = src;

    step_kernel<false><<<grid, blk>>>(s0,   nullptr, vp, src + (size_t)1 * VOL, bufA, nullptr);
    step_kernel<false><<<grid, blk>>>(bufA, s0,      vp, src + (size_t)2 * VOL, bufB, nullptr);
    step_kernel<false><<<grid, blk>>>(bufB, bufA,    vp, src + (size_t)3 * VOL, bufA, nullptr);
    step_kernel<false><<<grid, blk>>>(bufA, bufB,    vp, src + (size_t)4 * VOL, bufB, nullptr);
    step_kernel<false><<<grid, blk>>>(bufB, bufA,    vp, src + (size_t)5 * VOL, bufA, nullptr);
    step_kernel<false><<<grid, blk>>>(bufA, bufB,    vp, src + (size_t)6 * VOL, bufB, nullptr);
    step_kernel<false><<<grid, blk>>>(bufB, bufA,    vp, src + (size_t)7 * VOL, bufA, nullptr);
    step_kernel<false><<<grid, blk>>>(bufA, bufB,    vp, src + (size_t)8 * VOL, bufB, nullptr);
    step_kernel<true><<<grid, blk>>>(bufB, bufA,     vp, src + (size_t)9 * VOL, outp, ref);

    if (has_scalars) {
        finalize_kernel<<<1, 1>>>((float*)d_out, VOL);
    }
}

// round 17
// speedup vs baseline: 1.3115x; 1.1855x over previous
#include <cuda_runtime.h>
#include <cuda_bf16.h>
#include <math.h>
#include <stdint.h>

// ---------------------------------------------------------------------------
// 25-pt (radius-4, 3-axis) wave stencil, 10 scan steps (first trivial),
// then loss = mean((out-ref)^2), max_abs = max|out-ref|.
// R17: EXACT R12 champion (two 3-deep cp.async rings, fill distance 2, one
// commit/body, wait_group 1, 6 blocks/SM, regs ~80) with ONE change:
// the q-head LDG (cur[z+5]) is issued BEFORE wait_group+barrier (it touches
// no smem ring -> race-free), gaining the wait duration of latency cover.
// ---------------------------------------------------------------------------

#define NN 192
#define PLANE (NN * NN)
#define VOL (NN * NN * NN)

#define TXT 16
#define TY 8
#define NTHR (TXT * TY)          // 128
#define SPANX (TXT * 4)          // 64 x-points per block
#define ZC 16
#define R  4

#define TILE_H (TY + 2 * R)      // 16
#define TILE_W 80                // padded row stride (R12-identical)
#define TILE_WU (SPANX + 2 * R)  // 72 floats used
#define FW4 (TILE_WU / 4)        // 18 float4 per row
#define NSLOT (TILE_H * FW4)     // 288 fill slots
#define NBUF 3
#define PWF (NTHR * 4)           // floats per pw field (512)

#define C0 ((float)(-205.0 / 72.0 / 400.0))
#define C1 ((float)(8.0 / 5.0 / 400.0))
#define C2 ((float)(-1.0 / 5.0 / 400.0))
#define C3 ((float)(8.0 / 315.0 / 400.0))
#define C4 ((float)(-1.0 / 560.0 / 400.0))

__device__ float g_bufA[VOL];
__device__ float g_bufB[VOL];
__device__ double g_sum;
__device__ unsigned int g_maxbits;

__global__ void init_accum_kernel() {
    g_sum = 0.0;
    g_maxbits = 0u;
}

__device__ __forceinline__ float4 ldg4(const float* p) {
    return *reinterpret_cast<const float4*>(p);
}
__device__ __forceinline__ float ldcs1(const float* p) {
    float v;
    asm volatile("ld.global.cs.f32 %0, [%1];" : "=f"(v) : "l"(p));
    return v;
}

// Stencil tile fill (cp.async, NO commit)
__device__ __forceinline__ void fill_plane(
    uint32_t sbase, const float* gplane, const int* goff, const int* sidx) {
#pragma unroll
    for (int k = 0; k < 3; k++) {
        if (sidx[k] >= 0) {
            const float* srcp = (goff[k] >= 0) ? (gplane + goff[k]) : gplane;
            int sz = (goff[k] >= 0) ? 16 : 0;
            asm volatile("cp.async.cg.shared.global [%0], [%1], 16, %2;"
                         :: "r"(sbase + (uint32_t)sidx[k] * 4u), "l"(srcp), "r"(sz));
        }
    }
}

// Pointwise fill: prev/vp/src quads for one plane (NO commit).
__device__ __forceinline__ void fill_pw(
    uint32_t pwbase, const float* prev, const float* vp, const float* src,
    int idx, bool hasprev, int tid) {
    uint32_t d = pwbase + (uint32_t)tid * 16u;
    if (hasprev) {
        asm volatile("cp.async.cg.shared.global [%0], [%1], 16;"
                     :: "r"(d), "l"(prev + idx));
    }
    asm volatile("cp.async.cg.shared.global [%0], [%1], 16;"
                 :: "r"(d + PWF * 4u), "l"(vp + idx));
    asm volatile("cp.async.cg.shared.global [%0], [%1], 16;"
                 :: "r"(d + 2u * PWF * 4u), "l"(src + idx));
}

// 25-pt laplacian for one plane from tile t + 9 z-queue values.
__device__ __forceinline__ float4 lap25(
    const float (&t)[TILE_H][TILE_W], int sx, int syc,
    const float4& qm4, const float4& qm3, const float4& qm2, const float4& qm1,
    const float4& qc,
    const float4& qp1, const float4& qp2, const float4& qp3, const float4& qp4) {

    float xs[12];
#pragma unroll
    for (int j = 0; j < 3; j++) {
        float4 v = *reinterpret_cast<const float4*>(&t[syc][sx - 4 + 4 * j]);
        xs[4 * j + 0] = v.x;
        xs[4 * j + 1] = v.y;
        xs[4 * j + 2] = v.z;
        xs[4 * j + 3] = v.w;
    }

    float lap[4];
    {
        const float* q4 = &qc.x;
#pragma unroll
        for (int p = 0; p < 4; p++) lap[p] = (3.0f * C0) * q4[p];
    }
    {
        float4 ym = *reinterpret_cast<const float4*>(&t[syc - 1][sx]);
        float4 yp = *reinterpret_cast<const float4*>(&t[syc + 1][sx]);
        const float* a = &ym.x; const float* b = &yp.x;
        const float* m = &qm1.x; const float* pl = &qp1.x;
#pragma unroll
        for (int p = 0; p < 4; p++)
            lap[p] += C1 * (m[p] + pl[p] + a[p] + b[p] + xs[p + 3] + xs[p + 5]);
    }
    {
        float4 ym = *reinterpret_cast<const float4*>(&t[syc - 2][sx]);
        float4 yp = *reinterpret_cast<const float4*>(&t[syc + 2][sx]);
        const float* a = &ym.x; const float* b = &yp.x;
        const float* m = &qm2.x; const float* pl = &qp2.x;
#pragma unroll
        for (int p = 0; p < 4; p++)
            lap[p] += C2 * (m[p] + pl[p] + a[p] + b[p] + xs[p + 2] + xs[p + 6]);
    }
    {
        float4 ym = *reinterpret_cast<const float4*>(&t[syc - 3][sx]);
        float4 yp = *reinterpret_cast<const float4*>(&t[syc + 3][sx]);
        const float* a = &ym.x; const float* b = &yp.x;
        const float* m = &qm3.x; const float* pl = &qp3.x;
#pragma unroll
        for (int p = 0; p < 4; p++)
            lap[p] += C3 * (m[p] + pl[p] + a[p] + b[p] + xs[p + 1] + xs[p + 7]);
    }
    {
        float4 ym = *reinterpret_cast<const float4*>(&t[syc - 4][sx]);
        float4 yp = *reinterpret_cast<const float4*>(&t[syc + 4][sx]);
        const float* a = &ym.x; const float* b = &yp.x;
        const float* m = &qm4.x; const float* pl = &qp4.x;
#pragma unroll
        for (int p = 0; p < 4; p++)
            lap[p] += C4 * (m[p] + pl[p] + a[p] + b[p] + xs[p] + xs[p + 8]);
    }
    return make_float4(lap[0], lap[1], lap[2], lap[3]);
}

// Body for plane z (R12 cadence; q-head LDG hoisted above the wait):
//  LDG(z+5) -> wait_group 1 -> barrier -> fill S(z+2)+PW(z+2), ONE commit
//  -> LDS pv/vv/sv -> compute -> store.
template <bool FINAL>
__device__ __forceinline__ void plane_body(
    const float* __restrict__ cur, const float* __restrict__ prev,
    const float* __restrict__ vp, const float* __restrict__ src,
    float* __restrict__ out, const float* __restrict__ ref,
    const float (&consume)[TILE_H][TILE_W],
    const float* pwcons,
    uint32_t fill_sb, uint32_t fill_pb,
    int z, bool hasprev,
    const int* goff, const int* sidx, int col, int tid,
    float4& qm4, float4& qm3, float4& qm2, float4& qm1, float4& qc,
    float4& qp1, float4& qp2, float4& qp3, float4& qp4,
    int sx, int syc,
    double& acc_s, float& acc_m) {

    const int idx = z * PLANE + col;

    // q-head prefetch for NEXT body (plane z+5) — no smem dependence, so it
    // is issued BEFORE the wait/barrier and covers their latency for free.
    float4 qn;
    {
        int zp = z + 5;
        qn = (zp < NN) ? ldg4(&cur[zp * PLANE + col]) : make_float4(0.f, 0.f, 0.f, 0.f);
    }

    asm volatile("cp.async.wait_group 1;" ::: "memory");
    __syncthreads();

    // fills for plane z+2 (slot consumed at body z-1 -> safe post-barrier)
    {
        int zf = z + 2; if (zf > NN - 1) zf = NN - 1;
        fill_plane(fill_sb, cur + zf * PLANE, goff, sidx);
        fill_pw(fill_pb, prev, vp, src, zf * PLANE + col, hasprev, tid);
        asm volatile("cp.async.commit_group;" ::: "memory");
    }

    const float4 pv = hasprev
        ? *reinterpret_cast<const float4*>(pwcons + 4 * tid)
        : make_float4(0.f, 0.f, 0.f, 0.f);
    const float4 vv = *reinterpret_cast<const float4*>(pwcons + PWF + 4 * tid);
    const float4 sv = *reinterpret_cast<const float4*>(pwcons + 2 * PWF + 4 * tid);

    float4 lp = lap25(consume, sx, syc, qm4, qm3, qm2, qm1, qc, qp1, qp2, qp3, qp4);

    float4 upd;
    {
        const float* q4 = &qc.x;
        const float* pvp = &pv.x; const float* vvp = &vv.x; const float* svp = &sv.x;
        const float* lpp = &lp.x; float* u = &upd.x;
#pragma unroll
        for (int p = 0; p < 4; p++)
            u[p] = 2.0f * q4[p] - pvp[p] + vvp[p] * lpp[p] + svp[p];
    }

    if (FINAL) {
        const float* u = &upd.x;
#pragma unroll
        for (int p = 0; p < 4; p++) {
            out[idx + p] = u[p];
            float e = u[p] - ldcs1(&ref[idx + p]);
            acc_s += (double)e * (double)e;
            acc_m = fmaxf(acc_m, fabsf(e));
        }
    } else {
        *reinterpret_cast<float4*>(&out[idx]) = upd;
    }

    qm4 = qn;   // rotation: becomes next body's qp4
}

template <bool FINAL>
__global__ void __launch_bounds__(NTHR, 6)
step_kernel(const float* __restrict__ cur,
            const float* __restrict__ prev,
            const float* __restrict__ vp,
            const float* __restrict__ src,
            float* __restrict__ out,
            const float* __restrict__ ref) {
    __shared__ float sp[NBUF][TILE_H][TILE_W];    // 3 x 5120 B
    __shared__ float pwr[NBUF][3 * PWF];          // 3 x 6144 B

    const int tx = threadIdx.x;
    const int ty = threadIdx.y;
    const int x0 = blockIdx.x * SPANX;
    const int y0 = blockIdx.y * TY;
    const int z0 = blockIdx.z * ZC;
    const int gx = x0 + 4 * tx;
    const int gy = y0 + ty;
    const int tid = ty * TXT + tx;
    const int col = gy * NN + gx;

    int goff[3], sidx[3];
#pragma unroll
    for (int k = 0; k < 3; k++) {
        int i = tid + k * NTHR;
        if (i < NSLOT) {
            int sy = i / FW4;
            int sxx = i - sy * FW4;
            int yy = y0 - R + sy;
            int xx = x0 - R + 4 * sxx;
            sidx[k] = sy * TILE_W + 4 * sxx;
            goff[k] = (xx >= 0 && xx + 3 < NN && yy >= 0 && yy < NN)
                          ? (yy * NN + xx) : -1;
        } else {
            sidx[k] = -1;
            goff[k] = -1;
        }
    }

    uint32_t sb[NBUF], pb[NBUF];
#pragma unroll
    for (int b = 0; b < NBUF; b++) {
        sb[b] = (uint32_t)__cvta_generic_to_shared(&sp[b][0][0]);
        pb[b] = (uint32_t)__cvta_generic_to_shared(&pwr[b][0]);
    }

    const bool hasprev = (prev != nullptr);

    // Prologue: groups for planes z0 (slot 0) and z0+1 (slot 1)
    fill_plane(sb[0], cur + z0 * PLANE, goff, sidx);
    fill_pw(pb[0], prev, vp, src, z0 * PLANE + col, hasprev, tid);
    asm volatile("cp.async.commit_group;" ::: "memory");
    fill_plane(sb[1], cur + (z0 + 1) * PLANE, goff, sidx);
    fill_pw(pb[1], prev, vp, src, (z0 + 1) * PLANE + col, hasprev, tid);
    asm volatile("cp.async.commit_group;" ::: "memory");

    // z-queue: 9 named registers, planes z0-4 .. z0+4
    float4 r0, r1, r2, r3, r4, r5, r6, r7, r8;
    {
        float4* rr[9] = {&r0, &r1, &r2, &r3, &r4, &r5, &r6, &r7, &r8};
#pragma unroll
        for (int k = 0; k < 9; k++) {
            int gz = z0 - R + k;
            *rr[k] = (gz >= 0 && gz < NN) ? ldg4(&cur[gz * PLANE + col])
                                          : make_float4(0.f, 0.f, 0.f, 0.f);
        }
    }

    const int sx = R + 4 * tx;
    const int syc = ty + R;

    double acc_s = 0.0;
    float acc_m = 0.0f;

    // 16 unrolled bodies. Consume slot I%3; fill slot (I+2)%3.
#define PB(I, A, B, C, D, E, F, G, H, J)                                      \
    plane_body<FINAL>(cur, prev, vp, src, out, ref,                          \
                      sp[(I) % 3], &pwr[(I) % 3][0],                         \
                      sb[((I) + 2) % 3], pb[((I) + 2) % 3],                  \
                      z0 + (I), hasprev, goff, sidx, col, tid,               \
                      r##A, r##B, r##C, r##D, r##E, r##F, r##G, r##H, r##J,  \
                      sx, syc, acc_s, acc_m)

    PB(0, 0, 1, 2, 3, 4, 5, 6, 7, 8);
    PB(1, 1, 2, 3, 4, 5, 6, 7, 8, 0);
    PB(2, 2, 3, 4, 5, 6, 7, 8, 0, 1);
    PB(3, 3, 4, 5, 6, 7, 8, 0, 1, 2);
    PB(4, 4, 5, 6, 7, 8, 0, 1, 2, 3);
    PB(5, 5, 6, 7, 8, 0, 1, 2, 3, 4);
    PB(6, 6, 7, 8, 0, 1, 2, 3, 4, 5);
    PB(7, 7, 8, 0, 1, 2, 3, 4, 5, 6);
    PB(8, 8, 0, 1, 2, 3, 4, 5, 6, 7);
    PB(9, 0, 1, 2, 3, 4, 5, 6, 7, 8);
    PB(10, 1, 2, 3, 4, 5, 6, 7, 8, 0);
    PB(11, 2, 3, 4, 5, 6, 7, 8, 0, 1);
    PB(12, 3, 4, 5, 6, 7, 8, 0, 1, 2);
    PB(13, 4, 5, 6, 7, 8, 0, 1, 2, 3);
    PB(14, 5, 6, 7, 8, 0, 1, 2, 3, 4);
    PB(15, 6, 7, 8, 0, 1, 2, 3, 4, 5);
#undef PB

    if (FINAL) {
#pragma unroll
        for (int o = 16; o > 0; o >>= 1) {
            acc_s += __shfl_down_sync(0xFFFFFFFFu, acc_s, o);
            acc_m = fmaxf(acc_m, __shfl_down_sync(0xFFFFFFFFu, acc_m, o));
        }
        __shared__ double ss[4];
        __shared__ float sm[4];
        int lane = tid & 31;
        int w = tid >> 5;
        if (lane == 0) { ss[w] = acc_s; sm[w] = acc_m; }
        __syncthreads();
        if (w == 0) {
            acc_s = (lane < 4) ? ss[lane] : 0.0;
            acc_m = (lane < 4) ? sm[lane] : 0.0f;
#pragma unroll
            for (int o = 2; o > 0; o >>= 1) {
                acc_s += __shfl_down_sync(0xFFFFFFFFu, acc_s, o);
                acc_m = fmaxf(acc_m, __shfl_down_sync(0xFFFFFFFFu, acc_m, o));
            }
            if (lane == 0) {
                atomicAdd(&g_sum, acc_s);
                atomicMax(&g_maxbits, __float_as_uint(acc_m));
            }
        }
    }
}

__global__ void finalize_kernel(float* d_out, int n) {
    d_out[0] = (float)(g_sum / (double)n);
    d_out[n + 1] = __uint_as_float(g_maxbits);
}

extern "C" void kernel_launch(void* const* d_in, const int* in_sizes, int n_in,
                              void* d_out, int out_size) {
    const float* vp  = (const float*)d_in[0];
    const float* src = (const float*)d_in[1];
    const float* ref = (const float*)d_in[2];

    static float* bufA = nullptr;
    static float* bufB = nullptr;
    if (!bufA) {
        cudaGetSymbolAddress((void**)&bufA, g_bufA);
        cudaGetSymbolAddress((void**)&bufB, g_bufB);
    }

    const bool has_scalars = (out_size >= VOL + 2);
    float* outp = has_scalars ? ((float*)d_out + 1) : (float*)d_out;

    dim3 blk(TXT, TY);
    dim3 grid(NN / SPANX, NN / TY, NN / ZC);   // (3, 24, 12) = 864 blocks

    init_accum_kernel<<<1, 1>>>();

    const float* s0 = src;

    step_kernel<false><<<grid, blk>>>(s0,   nullptr, vp, src + (size_t)1 * VOL, bufA, nullptr);
    step_kernel<false><<<grid, blk>>>(bufA, s0,      vp, src + (size_t)2 * VOL, bufB, nullptr);
    step_kernel<false><<<grid, blk>>>(bufB, bufA,    vp, src + (size_t)3 * VOL, bufA, nullptr);
    step_kernel<false><<<grid, blk>>>(bufA, bufB,    vp, src + (size_t)4 * VOL, bufB, nullptr);
    step_kernel<false><<<grid, blk>>>(bufB, bufA,    vp, src + (size_t)5 * VOL, bufA, nullptr);
    step_kernel<false><<<grid, blk>>>(bufA, bufB,    vp, src + (size_t)6 * VOL, bufB, nullptr);
    step_kernel<false><<<grid, blk>>>(bufB, bufA,    vp, src + (size_t)7 * VOL, bufA, nullptr);
    step_kernel<false><<<grid, blk>>>(bufA, bufB,    vp, src + (size_t)8 * VOL, bufB, nullptr);
    step_kernel<true><<<grid, blk>>>(bufB, bufA,     vp, src + (size_t)9 * VOL, outp, ref);

    if (has_scalars) {
        finalize_kernel<<<1, 1>>>((float*)d_out, VOL);
    }
}